// round 4
// baseline (speedup 1.0000x reference)
#include <cuda_runtime.h>
#include <math.h>

#define Bv 256
#define Sv 512
#define Avv 64
#define Hv 1024
#define Zv 256
#define H3 3072
#define KS1 4
#define KS2 8

// ---------------- device scratch (static: no allocations) ----------------
__device__ float g_hbuf[2][Bv * Hv];
__device__ float g_PX[Avv * Hv];
__device__ float g_ENCX[Avv * Hv];
__device__ float g_GIX[Avv * H3];
__device__ float g_h1encp[KS1][Bv * Hv];
__device__ float g_h1prip[KS1][Bv * Hv];
__device__ float g_ghp[KS1][Bv * H3];
__device__ float g_gip[KS1][Bv * H3];
__device__ float g_hdencp[KS2][Bv * Zv];
__device__ float g_hdprip[KS2][Bv * Zv];
__device__ float g_zbuf[Bv * Zv];
__device__ float g_pz[Bv * Hv];
__device__ float g_fh1[Bv * Hv];
__device__ float g_fpri[Bv * Zv];
__device__ float g_decb[Bv * Hv];
__device__ double g_kldp[1024];
__device__ unsigned g_arrive, g_release, g_work;

// ---------------- helpers ----------------
__device__ __forceinline__ float softplusf(float x) {
    return x > 0.f ? x + log1pf(expf(-x)) : log1pf(expf(x));
}
__device__ __forceinline__ float sigmoidf(float x) {
    return 1.f / (1.f + expf(-x));
}

// grid-wide barrier. Also resets the work counter for the next phase.
// __threadfence() (gpu scope) emits CCTL.IVALL on sm_103a -> L1D refreshed.
__device__ __forceinline__ void grid_sync() {
    __syncthreads();
    if (threadIdx.x == 0) {
        __threadfence();
        volatile unsigned* rel = &g_release;
        unsigned gen = *rel;
        if (atomicAdd(&g_arrive, 1u) == gridDim.x - 1u) {
            g_arrive = 0u;
            g_work = 0u;
            __threadfence();
            atomicAdd(&g_release, 1u);
        } else {
            while (*rel == gen) __nanosleep(64);
        }
    }
    __syncthreads();
    __threadfence();
}

__device__ __forceinline__ int next_job(int* sJob) {
    __syncthreads();
    if (threadIdx.x == 0) *sJob = (int)atomicAdd(&g_work, 1u);
    __syncthreads();
    return *sJob;
}

// ---------------- 64x64 fp32 tile: acc += A[64,K] @ W[64,K]^T ----------------
// 256 threads, thread-tile 4x4, BK=16, register double-buffered global loads.
__device__ __forceinline__ void mm64(
    const float* __restrict__ A, int lda,
    const float* __restrict__ W, int ldw,
    int K, float (&acc)[4][4],
    float (*As)[68], float (*Ws)[68])
{
    const int tid = threadIdx.x;
    const int lr = tid >> 2, lc = (tid & 3) << 2;
    const int tx = tid & 15, ty = tid >> 4;
    const float* pa = A + (size_t)lr * lda + lc;
    const float* pw = W + (size_t)lr * ldw + lc;
    float4 av = *(const float4*)pa;
    float4 wv = *(const float4*)pw;
    for (int k0 = 0; k0 < K; k0 += 16) {
        __syncthreads();
        As[lc + 0][lr] = av.x; As[lc + 1][lr] = av.y;
        As[lc + 2][lr] = av.z; As[lc + 3][lr] = av.w;
        Ws[lc + 0][lr] = wv.x; Ws[lc + 1][lr] = wv.y;
        Ws[lc + 2][lr] = wv.z; Ws[lc + 3][lr] = wv.w;
        __syncthreads();
        if (k0 + 16 < K) {
            av = *(const float4*)(pa + k0 + 16);
            wv = *(const float4*)(pw + k0 + 16);
        }
#pragma unroll
        for (int k = 0; k < 16; k++) {
            float4 a = *(const float4*)&As[k][ty << 2];
            float4 b = *(const float4*)&Ws[k][tx << 2];
            acc[0][0] += a.x * b.x; acc[0][1] += a.x * b.y; acc[0][2] += a.x * b.z; acc[0][3] += a.x * b.w;
            acc[1][0] += a.y * b.x; acc[1][1] += a.y * b.y; acc[1][2] += a.y * b.z; acc[1][3] += a.y * b.w;
            acc[2][0] += a.z * b.x; acc[2][1] += a.z * b.y; acc[2][2] += a.z * b.z; acc[2][3] += a.z * b.w;
            acc[3][0] += a.w * b.x; acc[3][1] += a.w * b.y; acc[3][2] += a.w * b.z; acc[3][3] += a.w * b.w;
        }
    }
}

// Head-GEMM tile: A is built on the fly as relu(sum of KS1 partials + bias [+ tab[x]]).
// P pre-offset (m0*Hv + kofs); b1 pre-offset (+kofs); tab pre-offset (+kofs) or null;
// xc pre-offset (x + m0*Sv + t); W pre-offset (n0*ldw + kofs).
__device__ __forceinline__ void mm64_head(
    const float* __restrict__ P, int pstride,
    const float* __restrict__ b1,
    const float* __restrict__ tab, const int* __restrict__ xc,
    const float* __restrict__ W, int ldw,
    int K, float (&acc)[4][4],
    float (*As)[68], float (*Ws)[68])
{
    const int tid = threadIdx.x;
    const int lr = tid >> 2, lc = (tid & 3) << 2;
    const int tx = tid & 15, ty = tid >> 4;
    const float* p0 = P + (size_t)lr * Hv + lc;
    const float* pw = W + (size_t)lr * ldw + lc;
    const float* pt = nullptr;
    if (tab) pt = tab + (size_t)xc[lr * Sv] * Hv + lc;
    for (int k0 = 0; k0 < K; k0 += 16) {
        float4 a0 = *(const float4*)(p0 + k0);
        float4 a1 = *(const float4*)(p0 + pstride + k0);
        float4 a2 = *(const float4*)(p0 + 2 * pstride + k0);
        float4 a3 = *(const float4*)(p0 + 3 * pstride + k0);
        float4 bb = *(const float4*)(b1 + k0 + lc);
        float4 wv = *(const float4*)(pw + k0);
        float4 av;
        av.x = a0.x + a1.x + a2.x + a3.x + bb.x;
        av.y = a0.y + a1.y + a2.y + a3.y + bb.y;
        av.z = a0.z + a1.z + a2.z + a3.z + bb.z;
        av.w = a0.w + a1.w + a2.w + a3.w + bb.w;
        if (pt) {
            float4 tv = *(const float4*)(pt + k0);
            av.x += tv.x; av.y += tv.y; av.z += tv.z; av.w += tv.w;
        }
        av.x = fmaxf(av.x, 0.f); av.y = fmaxf(av.y, 0.f);
        av.z = fmaxf(av.z, 0.f); av.w = fmaxf(av.w, 0.f);
        __syncthreads();
        As[lc + 0][lr] = av.x; As[lc + 1][lr] = av.y;
        As[lc + 2][lr] = av.z; As[lc + 3][lr] = av.w;
        Ws[lc + 0][lr] = wv.x; Ws[lc + 1][lr] = wv.y;
        Ws[lc + 2][lr] = wv.z; Ws[lc + 3][lr] = wv.w;
        __syncthreads();
#pragma unroll
        for (int k = 0; k < 16; k++) {
            float4 a = *(const float4*)&As[k][ty << 2];
            float4 b = *(const float4*)&Ws[k][tx << 2];
            acc[0][0] += a.x * b.x; acc[0][1] += a.x * b.y; acc[0][2] += a.x * b.z; acc[0][3] += a.x * b.w;
            acc[1][0] += a.y * b.x; acc[1][1] += a.y * b.y; acc[1][2] += a.y * b.z; acc[1][3] += a.y * b.w;
            acc[2][0] += a.z * b.x; acc[2][1] += a.z * b.y; acc[2][2] += a.z * b.z; acc[2][3] += a.z * b.w;
            acc[3][0] += a.w * b.x; acc[3][1] += a.w * b.y; acc[3][2] += a.w * b.z; acc[3][3] += a.w * b.w;
        }
    }
}

// C pre-offset to (m0, n0)
__device__ __forceinline__ void store_plain(float* C, int ldc, float (&acc)[4][4]) {
    const int tx = threadIdx.x & 15, ty = threadIdx.x >> 4;
#pragma unroll
    for (int i = 0; i < 4; i++) {
        float4 v = make_float4(acc[i][0], acc[i][1], acc[i][2], acc[i][3]);
        *(float4*)(C + (size_t)(ty * 4 + i) * ldc + tx * 4) = v;
    }
}
// bias pre-offset (+n0); relu flag
__device__ __forceinline__ void store_epi(float* C, int ldc, float (&acc)[4][4],
                                          const float* __restrict__ bias, int relu) {
    const int tx = threadIdx.x & 15, ty = threadIdx.x >> 4;
    float4 bb = *(const float4*)(bias + tx * 4);
#pragma unroll
    for (int i = 0; i < 4; i++) {
        float4 v = make_float4(acc[i][0] + bb.x, acc[i][1] + bb.y,
                               acc[i][2] + bb.z, acc[i][3] + bb.w);
        if (relu) {
            v.x = fmaxf(v.x, 0.f); v.y = fmaxf(v.y, 0.f);
            v.z = fmaxf(v.z, 0.f); v.w = fmaxf(v.w, 0.f);
        }
        *(float4*)(C + (size_t)(ty * 4 + i) * ldc + tx * 4) = v;
    }
}

// ---------------- the one persistent kernel ----------------
__global__ void __launch_bounds__(256, 1) vrnn_persistent(
    const int* __restrict__ x, const float* __restrict__ h0,
    const float* __restrict__ eps,
    const float* __restrict__ phi_x_w, const float* __restrict__ phi_x_b,
    const float* __restrict__ enc_w1, const float* __restrict__ enc_b1,
    const float* __restrict__ enc_w2, const float* __restrict__ enc_b2,
    const float* __restrict__ pri_w1, const float* __restrict__ pri_b1,
    const float* __restrict__ pri_w2, const float* __restrict__ pri_b2,
    const float* __restrict__ phi_z_w, const float* __restrict__ phi_z_b,
    const float* __restrict__ dec_w, const float* __restrict__ dec_b,
    const float* __restrict__ act_w, const float* __restrict__ act_b,
    const float* __restrict__ wih, const float* __restrict__ whh,
    const float* __restrict__ bih, const float* __restrict__ bhh,
    float* __restrict__ out, int out_size)
{
    __shared__ float As[16][68], Ws[16][68];
    __shared__ int sJob;
    __shared__ double sRed[8];

    const int tid = threadIdx.x;
    const int gtid = blockIdx.x * blockDim.x + tid;
    const int nthr = gridDim.x * blockDim.x;
    double kacc = 0.0;

    // ---- P0: PX table (elementwise) ----
    for (int i = gtid; i < Avv * Hv; i += nthr) {
        int a = i >> 10, j = i & 1023;
        g_PX[i] = fmaxf(phi_x_w[(size_t)j * Avv + a] + phi_x_b[j], 0.f);
    }
    grid_sync();

    // ---- P1: ENCX (16 tiles) + GIX (48 tiles), K=1024, m=64 single strip ----
    for (;;) {
        int j = next_job(&sJob);
        if (j >= 64) break;
        float acc[4][4] = {};
        if (j < 16) {
            mm64(g_PX, Hv, enc_w1 + (size_t)j * 64 * 2048, 2048, Hv, acc, As, Ws);
            store_plain(g_ENCX + j * 64, Hv, acc);
        } else {
            int nb = j - 16;
            mm64(g_PX, Hv, wih + (size_t)nb * 64 * 2048, 2048, Hv, acc, As, Ws);
            store_plain(g_GIX + nb * 64, H3, acc);
        }
    }
    grid_sync();

    // ================= recurrent steps =================
    for (int t = 0; t < Sv; t++) {
        const float* hcur = (t == 0) ? h0 : g_hbuf[(t + 1) & 1];
        float* hnext = g_hbuf[t & 1];

        // ---- S1: h1enc partials (256) | h1pri partials (256) | gh partials (768) ----
        for (;;) {
            int j = next_job(&sJob);
            if (j >= 1280) break;
            float acc[4][4] = {};
            if (j < 256) {
                int ks = j & 3, r = j >> 2, mb = r >> 4, nb = r & 15;
                mm64(hcur + (size_t)mb * 64 * Hv + ks * 256, Hv,
                     enc_w1 + (size_t)nb * 64 * 2048 + 1024 + ks * 256, 2048,
                     256, acc, As, Ws);
                store_plain(g_h1encp[ks] + (size_t)mb * 64 * Hv + nb * 64, Hv, acc);
            } else if (j < 512) {
                int q = j - 256;
                int ks = q & 3, r = q >> 2, mb = r >> 4, nb = r & 15;
                mm64(hcur + (size_t)mb * 64 * Hv + ks * 256, Hv,
                     pri_w1 + (size_t)nb * 64 * Hv + ks * 256, Hv,
                     256, acc, As, Ws);
                store_plain(g_h1prip[ks] + (size_t)mb * 64 * Hv + nb * 64, Hv, acc);
            } else {
                int q = j - 512;
                int ks = q & 3, r = q >> 2, mb = r / 48, nb = r % 48;
                mm64(hcur + (size_t)mb * 64 * Hv + ks * 256, Hv,
                     whh + (size_t)nb * 64 * Hv + ks * 256, Hv,
                     256, acc, As, Ws);
                store_plain(g_ghp[ks] + (size_t)mb * 64 * H3 + nb * 64, H3, acc);
            }
        }
        grid_sync();

        // ---- S2: head GEMM partials, K split 8 (enc 128 | pri 128 jobs) ----
        for (;;) {
            int j = next_job(&sJob);
            if (j >= 256) break;
            float acc[4][4] = {};
            int jj = j & 127, typ = j >> 7;
            int ks = jj & 7, r = jj >> 3, mb = r >> 2, zb = r & 3;
            int kofs = ks * 128, m0 = mb * 64;
            if (typ == 0) {
                mm64_head(g_h1encp[0] + (size_t)m0 * Hv + kofs, Bv * Hv,
                          enc_b1 + kofs, g_ENCX + kofs, x + (size_t)m0 * Sv + t,
                          enc_w2 + (size_t)zb * 64 * Hv + kofs, Hv,
                          128, acc, As, Ws);
                store_plain(g_hdencp[ks] + (size_t)m0 * Zv + zb * 64, Zv, acc);
            } else {
                mm64_head(g_h1prip[0] + (size_t)m0 * Hv + kofs, Bv * Hv,
                          pri_b1 + kofs, nullptr, nullptr,
                          pri_w2 + (size_t)zb * 64 * Hv + kofs, Hv,
                          128, acc, As, Ws);
                store_plain(g_hdprip[ks] + (size_t)m0 * Zv + zb * 64, Zv, acc);
            }
        }
        grid_sync();

        // ---- S3: softplus + KLD + z (elementwise over B*Z) ----
        {
            const float* ep = eps + (size_t)t * Bv * Zv;
            for (int i = gtid; i < Bv * Zv; i += nthr) {
                int zc = i & 255;
                float e = enc_b2[zc], p = pri_b2[zc];
#pragma unroll
                for (int q = 0; q < KS2; q++) { e += g_hdencp[q][i]; p += g_hdprip[q][i]; }
                float es = softplusf(e), ps = softplusf(p);
                float d = e - p;
                kacc += (double)(2.f * (logf(ps) - logf(es))
                                 + (es * es + d * d) / (ps * ps) - 1.f);
                g_zbuf[i] = ep[i] * es + e;
            }
        }
        grid_sync();

        // ---- S4: pz = relu(z @ phi_z_w^T + b) (64 tiles, K=256) ----
        for (;;) {
            int j = next_job(&sJob);
            if (j >= 64) break;
            float acc[4][4] = {};
            int mb = j >> 4, nb = j & 15;
            mm64(g_zbuf + (size_t)mb * 64 * Zv, Zv,
                 phi_z_w + (size_t)nb * 64 * Zv, Zv, Zv, acc, As, Ws);
            store_epi(g_pz + (size_t)mb * 64 * Hv + nb * 64, Hv, acc,
                      phi_z_b + nb * 64, 1);
        }
        grid_sync();

        // ---- S5: gi partials = pz @ wihR^T, K split 4 (768 jobs) ----
        for (;;) {
            int j = next_job(&sJob);
            if (j >= 768) break;
            float acc[4][4] = {};
            int ks = j & 3, r = j >> 2, mb = r / 48, nb = r % 48;
            mm64(g_pz + (size_t)mb * 64 * Hv + ks * 256, Hv,
                 wih + (size_t)nb * 64 * 2048 + 1024 + ks * 256, 2048,
                 256, acc, As, Ws);
            store_plain(g_gip[ks] + (size_t)mb * 64 * H3 + nb * 64, H3, acc);
        }
        grid_sync();

        // ---- S6: GRU gates (elementwise over B*H) ----
        for (int i = gtid; i < Bv * Hv; i += nthr) {
            int m = i >> 10, j = i & 1023;
            int xm = x[(size_t)m * Sv + t];
            size_t b3 = (size_t)m * H3;
            size_t tb = (size_t)xm * H3;
            float gr = bih[j] + g_GIX[tb + j];
            float gz = bih[Hv + j] + g_GIX[tb + Hv + j];
            float gn = bih[2 * Hv + j] + g_GIX[tb + 2 * Hv + j];
            float hr = bhh[j], hz = bhh[Hv + j], hn = bhh[2 * Hv + j];
#pragma unroll
            for (int q = 0; q < KS1; q++) {
                gr += g_gip[q][b3 + j];        hr += g_ghp[q][b3 + j];
                gz += g_gip[q][b3 + Hv + j];   hz += g_ghp[q][b3 + Hv + j];
                gn += g_gip[q][b3 + 2 * Hv + j]; hn += g_ghp[q][b3 + 2 * Hv + j];
            }
            float r = sigmoidf(gr + hr);
            float zg = sigmoidf(gz + hz);
            float n = tanhf(gn + r * hn);
            hnext[i] = (1.f - zg) * n + zg * hcur[i];
        }
        grid_sync();
    }

    // ================= epilogue =================
    const float* hF = g_hbuf[1];

    // E1: fh1 = relu(hF @ pri_w1^T + b) (64 tiles K=1024)
    for (;;) {
        int j = next_job(&sJob);
        if (j >= 64) break;
        float acc[4][4] = {};
        int mb = j >> 4, nb = j & 15;
        mm64(hF + (size_t)mb * 64 * Hv, Hv,
             pri_w1 + (size_t)nb * 64 * Hv, Hv, Hv, acc, As, Ws);
        store_epi(g_fh1 + (size_t)mb * 64 * Hv + nb * 64, Hv, acc, pri_b1 + nb * 64, 1);
    }
    grid_sync();

    // E2: fpri = fh1 @ pri_w2^T + b (16 tiles K=1024)
    for (;;) {
        int j = next_job(&sJob);
        if (j >= 16) break;
        float acc[4][4] = {};
        int mb = j >> 2, nb = j & 3;
        mm64(g_fh1 + (size_t)mb * 64 * Hv, Hv,
             pri_w2 + (size_t)nb * 64 * Hv, Hv, Hv, acc, As, Ws);
        store_epi(g_fpri + (size_t)mb * 64 * Zv + nb * 64, Zv, acc, pri_b2 + nb * 64, 0);
    }
    grid_sync();

    // E3: z = eps[S]*softplus(pri) + pri
    {
        const float* ep = eps + (size_t)Sv * Bv * Zv;
        for (int i = gtid; i < Bv * Zv; i += nthr) {
            float p = g_fpri[i];
            g_zbuf[i] = ep[i] * softplusf(p) + p;
        }
    }
    grid_sync();

    // E4: pz = relu(z @ phi_z_w^T + b)
    for (;;) {
        int j = next_job(&sJob);
        if (j >= 64) break;
        float acc[4][4] = {};
        int mb = j >> 4, nb = j & 15;
        mm64(g_zbuf + (size_t)mb * 64 * Zv, Zv,
             phi_z_w + (size_t)nb * 64 * Zv, Zv, Zv, acc, As, Ws);
        store_epi(g_pz + (size_t)mb * 64 * Hv + nb * 64, Hv, acc, phi_z_b + nb * 64, 1);
    }
    grid_sync();

    // E5: dec = relu(pz @ dec_wL^T + hF @ dec_wR^T + b) (64 dual tiles)
    for (;;) {
        int j = next_job(&sJob);
        if (j >= 64) break;
        float acc[4][4] = {};
        int mb = j >> 4, nb = j & 15;
        mm64(g_pz + (size_t)mb * 64 * Hv, Hv,
             dec_w + (size_t)nb * 64 * 2048, 2048, Hv, acc, As, Ws);
        mm64(hF + (size_t)mb * 64 * Hv, Hv,
             dec_w + (size_t)nb * 64 * 2048 + 1024, 2048, Hv, acc, As, Ws);
        store_epi(g_decb + (size_t)mb * 64 * Hv + nb * 64, Hv, acc, dec_b + nb * 64, 1);
    }
    grid_sync();

    // E6: pred_act = dec @ act_w^T + b -> out (4 tiles), then per-block kld partial
    for (;;) {
        int j = next_job(&sJob);
        if (j >= 4) break;
        float acc[4][4] = {};
        mm64(g_decb + (size_t)j * 64 * Hv, Hv, act_w, Hv, Hv, acc, As, Ws);
        store_epi(out + (size_t)j * 64 * Avv, Avv, acc, act_b, 0);
    }
    // per-block KLD partial (deterministic fixed-order reduction)
    {
        double v = kacc;
#pragma unroll
        for (int off = 16; off > 0; off >>= 1)
            v += __shfl_down_sync(0xffffffffu, v, off);
        if ((tid & 31) == 0) sRed[tid >> 5] = v;
        __syncthreads();
        if (tid == 0) {
            double s = 0.0;
            for (int w = 0; w < 8; w++) s += sRed[w];
            g_kldp[blockIdx.x] = s;
        }
    }
    grid_sync();

    // E7: block 0 sums kld partials in fixed order
    if (blockIdx.x == 0 && tid == 0) {
        double s = 0.0;
        for (unsigned b = 0; b < gridDim.x; b++) s += g_kldp[b];
        out[out_size - 1] = (float)(0.5 * s);
    }
}

// ---------------- host launch: ONE kernel node ----------------
extern "C" void kernel_launch(void* const* d_in, const int* in_sizes, int n_in,
                              void* d_out, int out_size)
{
    int dev = 0;
    cudaGetDevice(&dev);
    int sms = 0;
    cudaDeviceGetAttribute(&sms, cudaDevAttrMultiProcessorCount, dev);
    if (sms < 1) sms = 148;
    if (sms > 1024) sms = 1024;

    vrnn_persistent<<<sms, 256>>>(
        (const int*)d_in[0], (const float*)d_in[1], (const float*)d_in[2],
        (const float*)d_in[3], (const float*)d_in[4],
        (const float*)d_in[5], (const float*)d_in[6],
        (const float*)d_in[7], (const float*)d_in[8],
        (const float*)d_in[9], (const float*)d_in[10],
        (const float*)d_in[11], (const float*)d_in[12],
        (const float*)d_in[13], (const float*)d_in[14],
        (const float*)d_in[15], (const float*)d_in[16],
        (const float*)d_in[17], (const float*)d_in[18],
        (const float*)d_in[19], (const float*)d_in[20],
        (const float*)d_in[21], (const float*)d_in[22],
        (float*)d_out, out_size);
}

// round 5
// speedup vs baseline: 1.0034x; 1.0034x over previous
#include <cuda_runtime.h>
#include <math.h>

#define Bv 256
#define Sv 512
#define Avv 64
#define Hv 1024
#define Zv 256
#define H3 3072
#define KS1 4
#define KS2 8

// ---------------- device scratch (static: no allocations) ----------------
__device__ float g_hbuf[2][Bv * Hv];
__device__ float g_PX[Avv * Hv];
__device__ float g_ENCX[Avv * Hv];
__device__ float g_GIX[Avv * H3];
__device__ float g_h1encp[KS1][Bv * Hv];
__device__ float g_h1prip[KS1][Bv * Hv];
__device__ float g_ghp[KS1][Bv * H3];
__device__ float g_gip[KS1][Bv * H3];
__device__ float g_hdencp[KS2][Bv * Zv];
__device__ float g_hdprip[KS2][Bv * Zv];
__device__ float g_zbuf[Bv * Zv];
__device__ float g_pz[Bv * Hv];
__device__ float g_fh1[Bv * Hv];
__device__ float g_fpri[Bv * Zv];
__device__ float g_decb[Bv * Hv];
__device__ double g_kldp[1024];
__device__ unsigned g_arrive, g_release, g_work;

// ---------------- helpers ----------------
__device__ __forceinline__ float softplusf(float x) {
    return x > 0.f ? x + log1pf(expf(-x)) : log1pf(expf(x));
}
__device__ __forceinline__ float sigmoidf(float x) {
    return 1.f / (1.f + expf(-x));
}

// grid-wide barrier. Also resets the work counter for the next phase.
// __threadfence() (gpu scope) emits CCTL.IVALL on sm_103a -> L1D refreshed.
__device__ __forceinline__ void grid_sync() {
    __syncthreads();
    if (threadIdx.x == 0) {
        __threadfence();
        volatile unsigned* rel = &g_release;
        unsigned gen = *rel;
        if (atomicAdd(&g_arrive, 1u) == gridDim.x - 1u) {
            g_arrive = 0u;
            g_work = 0u;
            __threadfence();
            atomicAdd(&g_release, 1u);
        } else {
            while (*rel == gen) __nanosleep(64);
        }
    }
    __syncthreads();
    __threadfence();
}

__device__ __forceinline__ int next_job(int* sJob) {
    __syncthreads();
    if (threadIdx.x == 0) *sJob = (int)atomicAdd(&g_work, 1u);
    __syncthreads();
    return *sJob;
}

// ---------------- 64x64 fp32 tile: acc += A[64,K] @ W[64,K]^T ----------------
// 256 threads, thread-tile 4x4, BK=16, register double-buffered global loads.
__device__ __forceinline__ void mm64(
    const float* __restrict__ A, int lda,
    const float* __restrict__ W, int ldw,
    int K, float (&acc)[4][4],
    float (*As)[68], float (*Ws)[68])
{
    const int tid = threadIdx.x;
    const int lr = tid >> 2, lc = (tid & 3) << 2;
    const int tx = tid & 15, ty = tid >> 4;
    const float* pa = A + (size_t)lr * lda + lc;
    const float* pw = W + (size_t)lr * ldw + lc;
    float4 av = *(const float4*)pa;
    float4 wv = *(const float4*)pw;
    for (int k0 = 0; k0 < K; k0 += 16) {
        __syncthreads();
        As[lc + 0][lr] = av.x; As[lc + 1][lr] = av.y;
        As[lc + 2][lr] = av.z; As[lc + 3][lr] = av.w;
        Ws[lc + 0][lr] = wv.x; Ws[lc + 1][lr] = wv.y;
        Ws[lc + 2][lr] = wv.z; Ws[lc + 3][lr] = wv.w;
        __syncthreads();
        if (k0 + 16 < K) {
            av = *(const float4*)(pa + k0 + 16);
            wv = *(const float4*)(pw + k0 + 16);
        }
#pragma unroll
        for (int k = 0; k < 16; k++) {
            float4 a = *(const float4*)&As[k][ty << 2];
            float4 b = *(const float4*)&Ws[k][tx << 2];
            acc[0][0] += a.x * b.x; acc[0][1] += a.x * b.y; acc[0][2] += a.x * b.z; acc[0][3] += a.x * b.w;
            acc[1][0] += a.y * b.x; acc[1][1] += a.y * b.y; acc[1][2] += a.y * b.z; acc[1][3] += a.y * b.w;
            acc[2][0] += a.z * b.x; acc[2][1] += a.z * b.y; acc[2][2] += a.z * b.z; acc[2][3] += a.z * b.w;
            acc[3][0] += a.w * b.x; acc[3][1] += a.w * b.y; acc[3][2] += a.w * b.z; acc[3][3] += a.w * b.w;
        }
    }
}

// Head-GEMM tile: A is built on the fly as relu(sum of KS1 partials + bias [+ tab[x]]).
// P pre-offset (m0*Hv + kofs); b1 pre-offset (+kofs); tab pre-offset (+kofs) or null;
// xc pre-offset (x + m0*Sv + t); W pre-offset (n0*ldw + kofs).
__device__ __forceinline__ void mm64_head(
    const float* __restrict__ P, int pstride,
    const float* __restrict__ b1,
    const float* __restrict__ tab, const int* __restrict__ xc,
    const float* __restrict__ W, int ldw,
    int K, float (&acc)[4][4],
    float (*As)[68], float (*Ws)[68])
{
    const int tid = threadIdx.x;
    const int lr = tid >> 2, lc = (tid & 3) << 2;
    const int tx = tid & 15, ty = tid >> 4;
    const float* p0 = P + (size_t)lr * Hv + lc;
    const float* pw = W + (size_t)lr * ldw + lc;
    const float* pt = nullptr;
    if (tab) pt = tab + (size_t)xc[lr * Sv] * Hv + lc;
    for (int k0 = 0; k0 < K; k0 += 16) {
        float4 a0 = *(const float4*)(p0 + k0);
        float4 a1 = *(const float4*)(p0 + pstride + k0);
        float4 a2 = *(const float4*)(p0 + 2 * pstride + k0);
        float4 a3 = *(const float4*)(p0 + 3 * pstride + k0);
        float4 bb = *(const float4*)(b1 + k0 + lc);
        float4 wv = *(const float4*)(pw + k0);
        float4 av;
        av.x = a0.x + a1.x + a2.x + a3.x + bb.x;
        av.y = a0.y + a1.y + a2.y + a3.y + bb.y;
        av.z = a0.z + a1.z + a2.z + a3.z + bb.z;
        av.w = a0.w + a1.w + a2.w + a3.w + bb.w;
        if (pt) {
            float4 tv = *(const float4*)(pt + k0);
            av.x += tv.x; av.y += tv.y; av.z += tv.z; av.w += tv.w;
        }
        av.x = fmaxf(av.x, 0.f); av.y = fmaxf(av.y, 0.f);
        av.z = fmaxf(av.z, 0.f); av.w = fmaxf(av.w, 0.f);
        __syncthreads();
        As[lc + 0][lr] = av.x; As[lc + 1][lr] = av.y;
        As[lc + 2][lr] = av.z; As[lc + 3][lr] = av.w;
        Ws[lc + 0][lr] = wv.x; Ws[lc + 1][lr] = wv.y;
        Ws[lc + 2][lr] = wv.z; Ws[lc + 3][lr] = wv.w;
        __syncthreads();
#pragma unroll
        for (int k = 0; k < 16; k++) {
            float4 a = *(const float4*)&As[k][ty << 2];
            float4 b = *(const float4*)&Ws[k][tx << 2];
            acc[0][0] += a.x * b.x; acc[0][1] += a.x * b.y; acc[0][2] += a.x * b.z; acc[0][3] += a.x * b.w;
            acc[1][0] += a.y * b.x; acc[1][1] += a.y * b.y; acc[1][2] += a.y * b.z; acc[1][3] += a.y * b.w;
            acc[2][0] += a.z * b.x; acc[2][1] += a.z * b.y; acc[2][2] += a.z * b.z; acc[2][3] += a.z * b.w;
            acc[3][0] += a.w * b.x; acc[3][1] += a.w * b.y; acc[3][2] += a.w * b.z; acc[3][3] += a.w * b.w;
        }
    }
}

// C pre-offset to (m0, n0)
__device__ __forceinline__ void store_plain(float* C, int ldc, float (&acc)[4][4]) {
    const int tx = threadIdx.x & 15, ty = threadIdx.x >> 4;
#pragma unroll
    for (int i = 0; i < 4; i++) {
        float4 v = make_float4(acc[i][0], acc[i][1], acc[i][2], acc[i][3]);
        *(float4*)(C + (size_t)(ty * 4 + i) * ldc + tx * 4) = v;
    }
}
// bias pre-offset (+n0); relu flag
__device__ __forceinline__ void store_epi(float* C, int ldc, float (&acc)[4][4],
                                          const float* __restrict__ bias, int relu) {
    const int tx = threadIdx.x & 15, ty = threadIdx.x >> 4;
    float4 bb = *(const float4*)(bias + tx * 4);
#pragma unroll
    for (int i = 0; i < 4; i++) {
        float4 v = make_float4(acc[i][0] + bb.x, acc[i][1] + bb.y,
                               acc[i][2] + bb.z, acc[i][3] + bb.w);
        if (relu) {
            v.x = fmaxf(v.x, 0.f); v.y = fmaxf(v.y, 0.f);
            v.z = fmaxf(v.z, 0.f); v.w = fmaxf(v.w, 0.f);
        }
        *(float4*)(C + (size_t)(ty * 4 + i) * ldc + tx * 4) = v;
    }
}

// ---------------- the one persistent kernel ----------------
__global__ void __launch_bounds__(256, 1) vrnn_persistent(
    const int* __restrict__ x, const float* __restrict__ h0,
    const float* __restrict__ eps,
    const float* __restrict__ phi_x_w, const float* __restrict__ phi_x_b,
    const float* __restrict__ enc_w1, const float* __restrict__ enc_b1,
    const float* __restrict__ enc_w2, const float* __restrict__ enc_b2,
    const float* __restrict__ pri_w1, const float* __restrict__ pri_b1,
    const float* __restrict__ pri_w2, const float* __restrict__ pri_b2,
    const float* __restrict__ phi_z_w, const float* __restrict__ phi_z_b,
    const float* __restrict__ dec_w, const float* __restrict__ dec_b,
    const float* __restrict__ act_w, const float* __restrict__ act_b,
    const float* __restrict__ wih, const float* __restrict__ whh,
    const float* __restrict__ bih, const float* __restrict__ bhh,
    float* __restrict__ out, int out_size)
{
    __shared__ float As[16][68], Ws[16][68];
    __shared__ int sJob;
    __shared__ double sRed[8];

    const int tid = threadIdx.x;
    const int gtid = blockIdx.x * blockDim.x + tid;
    const int nthr = gridDim.x * blockDim.x;
    double kacc = 0.0;

    // ---- P0: PX table (elementwise) ----
    for (int i = gtid; i < Avv * Hv; i += nthr) {
        int a = i >> 10, j = i & 1023;
        g_PX[i] = fmaxf(phi_x_w[(size_t)j * Avv + a] + phi_x_b[j], 0.f);
    }
    grid_sync();

    // ---- P1: ENCX (16 tiles) + GIX (48 tiles), K=1024, m=64 single strip ----
    for (;;) {
        int j = next_job(&sJob);
        if (j >= 64) break;
        float acc[4][4] = {};
        if (j < 16) {
            mm64(g_PX, Hv, enc_w1 + (size_t)j * 64 * 2048, 2048, Hv, acc, As, Ws);
            store_plain(g_ENCX + j * 64, Hv, acc);
        } else {
            int nb = j - 16;
            mm64(g_PX, Hv, wih + (size_t)nb * 64 * 2048, 2048, Hv, acc, As, Ws);
            store_plain(g_GIX + nb * 64, H3, acc);
        }
    }
    grid_sync();

    // ================= recurrent steps =================
    for (int t = 0; t < Sv; t++) {
        const float* hcur = (t == 0) ? h0 : g_hbuf[(t + 1) & 1];
        float* hnext = g_hbuf[t & 1];

        // ---- S1: h1enc partials (256) | h1pri partials (256) | gh partials (768) ----
        for (;;) {
            int j = next_job(&sJob);
            if (j >= 1280) break;
            float acc[4][4] = {};
            if (j < 256) {
                int ks = j & 3, r = j >> 2, mb = r >> 4, nb = r & 15;
                mm64(hcur + (size_t)mb * 64 * Hv + ks * 256, Hv,
                     enc_w1 + (size_t)nb * 64 * 2048 + 1024 + ks * 256, 2048,
                     256, acc, As, Ws);
                store_plain(g_h1encp[ks] + (size_t)mb * 64 * Hv + nb * 64, Hv, acc);
            } else if (j < 512) {
                int q = j - 256;
                int ks = q & 3, r = q >> 2, mb = r >> 4, nb = r & 15;
                mm64(hcur + (size_t)mb * 64 * Hv + ks * 256, Hv,
                     pri_w1 + (size_t)nb * 64 * Hv + ks * 256, Hv,
                     256, acc, As, Ws);
                store_plain(g_h1prip[ks] + (size_t)mb * 64 * Hv + nb * 64, Hv, acc);
            } else {
                int q = j - 512;
                int ks = q & 3, r = q >> 2, mb = r / 48, nb = r % 48;
                mm64(hcur + (size_t)mb * 64 * Hv + ks * 256, Hv,
                     whh + (size_t)nb * 64 * Hv + ks * 256, Hv,
                     256, acc, As, Ws);
                store_plain(g_ghp[ks] + (size_t)mb * 64 * H3 + nb * 64, H3, acc);
            }
        }
        grid_sync();

        // ---- S2: head GEMM partials, K split 8 (enc 128 | pri 128 jobs) ----
        for (;;) {
            int j = next_job(&sJob);
            if (j >= 256) break;
            float acc[4][4] = {};
            int jj = j & 127, typ = j >> 7;
            int ks = jj & 7, r = jj >> 3, mb = r >> 2, zb = r & 3;
            int kofs = ks * 128, m0 = mb * 64;
            if (typ == 0) {
                mm64_head(g_h1encp[0] + (size_t)m0 * Hv + kofs, Bv * Hv,
                          enc_b1 + kofs, g_ENCX + kofs, x + (size_t)m0 * Sv + t,
                          enc_w2 + (size_t)zb * 64 * Hv + kofs, Hv,
                          128, acc, As, Ws);
                store_plain(g_hdencp[ks] + (size_t)m0 * Zv + zb * 64, Zv, acc);
            } else {
                mm64_head(g_h1prip[0] + (size_t)m0 * Hv + kofs, Bv * Hv,
                          pri_b1 + kofs, nullptr, nullptr,
                          pri_w2 + (size_t)zb * 64 * Hv + kofs, Hv,
                          128, acc, As, Ws);
                store_plain(g_hdprip[ks] + (size_t)m0 * Zv + zb * 64, Zv, acc);
            }
        }
        grid_sync();

        // ---- S3: softplus + KLD + z (elementwise over B*Z) ----
        {
            const float* ep = eps + (size_t)t * Bv * Zv;
            for (int i = gtid; i < Bv * Zv; i += nthr) {
                int zc = i & 255;
                float e = enc_b2[zc], p = pri_b2[zc];
#pragma unroll
                for (int q = 0; q < KS2; q++) { e += g_hdencp[q][i]; p += g_hdprip[q][i]; }
                float es = softplusf(e), ps = softplusf(p);
                float d = e - p;
                kacc += (double)(2.f * (logf(ps) - logf(es))
                                 + (es * es + d * d) / (ps * ps) - 1.f);
                g_zbuf[i] = ep[i] * es + e;
            }
        }
        grid_sync();

        // ---- S4: pz = relu(z @ phi_z_w^T + b) (64 tiles, K=256) ----
        for (;;) {
            int j = next_job(&sJob);
            if (j >= 64) break;
            float acc[4][4] = {};
            int mb = j >> 4, nb = j & 15;
            mm64(g_zbuf + (size_t)mb * 64 * Zv, Zv,
                 phi_z_w + (size_t)nb * 64 * Zv, Zv, Zv, acc, As, Ws);
            store_epi(g_pz + (size_t)mb * 64 * Hv + nb * 64, Hv, acc,
                      phi_z_b + nb * 64, 1);
        }
        grid_sync();

        // ---- S5: gi partials = pz @ wihR^T, K split 4 (768 jobs) ----
        for (;;) {
            int j = next_job(&sJob);
            if (j >= 768) break;
            float acc[4][4] = {};
            int ks = j & 3, r = j >> 2, mb = r / 48, nb = r % 48;
            mm64(g_pz + (size_t)mb * 64 * Hv + ks * 256, Hv,
                 wih + (size_t)nb * 64 * 2048 + 1024 + ks * 256, 2048,
                 256, acc, As, Ws);
            store_plain(g_gip[ks] + (size_t)mb * 64 * H3 + nb * 64, H3, acc);
        }
        grid_sync();

        // ---- S6: GRU gates (elementwise over B*H) ----
        for (int i = gtid; i < Bv * Hv; i += nthr) {
            int m = i >> 10, j = i & 1023;
            int xm = x[(size_t)m * Sv + t];
            size_t b3 = (size_t)m * H3;
            size_t tb = (size_t)xm * H3;
            float gr = bih[j] + g_GIX[tb + j];
            float gz = bih[Hv + j] + g_GIX[tb + Hv + j];
            float gn = bih[2 * Hv + j] + g_GIX[tb + 2 * Hv + j];
            float hr = bhh[j], hz = bhh[Hv + j], hn = bhh[2 * Hv + j];
#pragma unroll
            for (int q = 0; q < KS1; q++) {
                gr += g_gip[q][b3 + j];        hr += g_ghp[q][b3 + j];
                gz += g_gip[q][b3 + Hv + j];   hz += g_ghp[q][b3 + Hv + j];
                gn += g_gip[q][b3 + 2 * Hv + j]; hn += g_ghp[q][b3 + 2 * Hv + j];
            }
            float r = sigmoidf(gr + hr);
            float zg = sigmoidf(gz + hz);
            float n = tanhf(gn + r * hn);
            hnext[i] = (1.f - zg) * n + zg * hcur[i];
        }
        grid_sync();
    }

    // ================= epilogue =================
    const float* hF = g_hbuf[1];

    // E1: fh1 = relu(hF @ pri_w1^T + b) (64 tiles K=1024)
    for (;;) {
        int j = next_job(&sJob);
        if (j >= 64) break;
        float acc[4][4] = {};
        int mb = j >> 4, nb = j & 15;
        mm64(hF + (size_t)mb * 64 * Hv, Hv,
             pri_w1 + (size_t)nb * 64 * Hv, Hv, Hv, acc, As, Ws);
        store_epi(g_fh1 + (size_t)mb * 64 * Hv + nb * 64, Hv, acc, pri_b1 + nb * 64, 1);
    }
    grid_sync();

    // E2: fpri = fh1 @ pri_w2^T + b (16 tiles K=1024)
    for (;;) {
        int j = next_job(&sJob);
        if (j >= 16) break;
        float acc[4][4] = {};
        int mb = j >> 2, nb = j & 3;
        mm64(g_fh1 + (size_t)mb * 64 * Hv, Hv,
             pri_w2 + (size_t)nb * 64 * Hv, Hv, Hv, acc, As, Ws);
        store_epi(g_fpri + (size_t)mb * 64 * Zv + nb * 64, Zv, acc, pri_b2 + nb * 64, 0);
    }
    grid_sync();

    // E3: z = eps[S]*softplus(pri) + pri
    {
        const float* ep = eps + (size_t)Sv * Bv * Zv;
        for (int i = gtid; i < Bv * Zv; i += nthr) {
            float p = g_fpri[i];
            g_zbuf[i] = ep[i] * softplusf(p) + p;
        }
    }
    grid_sync();

    // E4: pz = relu(z @ phi_z_w^T + b)
    for (;;) {
        int j = next_job(&sJob);
        if (j >= 64) break;
        float acc[4][4] = {};
        int mb = j >> 4, nb = j & 15;
        mm64(g_zbuf + (size_t)mb * 64 * Zv, Zv,
             phi_z_w + (size_t)nb * 64 * Zv, Zv, Zv, acc, As, Ws);
        store_epi(g_pz + (size_t)mb * 64 * Hv + nb * 64, Hv, acc, phi_z_b + nb * 64, 1);
    }
    grid_sync();

    // E5: dec = relu(pz @ dec_wL^T + hF @ dec_wR^T + b) (64 dual tiles)
    for (;;) {
        int j = next_job(&sJob);
        if (j >= 64) break;
        float acc[4][4] = {};
        int mb = j >> 4, nb = j & 15;
        mm64(g_pz + (size_t)mb * 64 * Hv, Hv,
             dec_w + (size_t)nb * 64 * 2048, 2048, Hv, acc, As, Ws);
        mm64(hF + (size_t)mb * 64 * Hv, Hv,
             dec_w + (size_t)nb * 64 * 2048 + 1024, 2048, Hv, acc, As, Ws);
        store_epi(g_decb + (size_t)mb * 64 * Hv + nb * 64, Hv, acc, dec_b + nb * 64, 1);
    }
    grid_sync();

    // E6: pred_act = dec @ act_w^T + b -> out (4 tiles), then per-block kld partial
    for (;;) {
        int j = next_job(&sJob);
        if (j >= 4) break;
        float acc[4][4] = {};
        mm64(g_decb + (size_t)j * 64 * Hv, Hv, act_w, Hv, Hv, acc, As, Ws);
        store_epi(out + (size_t)j * 64 * Avv, Avv, acc, act_b, 0);
    }
    // per-block KLD partial (deterministic fixed-order reduction)
    {
        double v = kacc;
#pragma unroll
        for (int off = 16; off > 0; off >>= 1)
            v += __shfl_down_sync(0xffffffffu, v, off);
        if ((tid & 31) == 0) sRed[tid >> 5] = v;
        __syncthreads();
        if (tid == 0) {
            double s = 0.0;
            for (int w = 0; w < 8; w++) s += sRed[w];
            g_kldp[blockIdx.x] = s;
        }
    }
    grid_sync();

    // E7: block 0 sums kld partials in fixed order
    if (blockIdx.x == 0 && tid == 0) {
        double s = 0.0;
        for (unsigned b = 0; b < gridDim.x; b++) s += g_kldp[b];
        out[out_size - 1] = (float)(0.5 * s);
    }
}

// ---------------- host launch: ONE kernel node ----------------
extern "C" void kernel_launch(void* const* d_in, const int* in_sizes, int n_in,
                              void* d_out, int out_size)
{
    int dev = 0;
    cudaGetDevice(&dev);
    int sms = 0;
    cudaDeviceGetAttribute(&sms, cudaDevAttrMultiProcessorCount, dev);
    if (sms < 1) sms = 148;
    if (sms > 1024) sms = 1024;

    vrnn_persistent<<<sms, 256>>>(
        (const int*)d_in[0], (const float*)d_in[1], (const float*)d_in[2],
        (const float*)d_in[3], (const float*)d_in[4],
        (const float*)d_in[5], (const float*)d_in[6],
        (const float*)d_in[7], (const float*)d_in[8],
        (const float*)d_in[9], (const float*)d_in[10],
        (const float*)d_in[11], (const float*)d_in[12],
        (const float*)d_in[13], (const float*)d_in[14],
        (const float*)d_in[15], (const float*)d_in[16],
        (const float*)d_in[17], (const float*)d_in[18],
        (const float*)d_in[19], (const float*)d_in[20],
        (const float*)d_in[21], (const float*)d_in[22],
        (float*)d_out, out_size);
}